// round 14
// baseline (speedup 1.0000x reference)
#include <cuda_runtime.h>
#include <cuda_bf16.h>
#include <cstdint>

// Degree-2 Taylor attention with RPE via warp-level mma.sync (bf16 x3-split)
// + mod-128 rolling band ring + L1 prefetch + named wi-barriers.
// BI=64, BJ=64, 256 threads (8 warps), grid 16 x 16 = 256 CTAs, 2 CTAs/SM.

constexpr int NSEQ = 1024, BI = 64, BJ = 64, NT = NSEQ / BJ;
constexpr int RSTR = 130;   // ring stride in floats (128 slots + 2 slack)

// smem byte offsets
constexpr int Q_HI = 0,      Q_LO = 8192;    // 64x64 bf16
constexpr int K_HI = 16384,  K_LO = 24576;   // 64x64
constexpr int R_HI = 32768,  R_LO = 40960;   // 64 rpe rows
constexpr int V_HI = 49152,  V_LO = 57344;   // 64x64 natural
constexpr int S_HI = 65536,  S_LO = 73728;   // 64x64
constexpr int RING = 81920;                  // 64 x 130 f32 ring (+Dsm in slack)
constexpr int SMEM_BYTES = RING + 64 * RSTR * 4;   // 115200

#define SWZ(o) ((o) ^ ((((o) >> 7) & 7) << 4))

__device__ __forceinline__ uint32_t smem_u32(const void* p) {
    uint32_t a;
    asm("{ .reg .u64 t; cvta.to.shared.u64 t, %1; cvt.u32.u64 %0, t; }"
        : "=r"(a) : "l"(p));
    return a;
}
__device__ __forceinline__ void named_bar(int id) {
    asm volatile("bar.sync %0, 128;" :: "r"(id) : "memory");
}
__device__ __forceinline__ void ldmA(uint32_t a[4], uint32_t addr) {
    asm volatile("ldmatrix.sync.aligned.m8n8.x4.shared.b16 {%0,%1,%2,%3}, [%4];"
                 : "=r"(a[0]), "=r"(a[1]), "=r"(a[2]), "=r"(a[3]) : "r"(addr));
}
__device__ __forceinline__ void ldmB(uint32_t b[2], uint32_t addr) {
    asm volatile("ldmatrix.sync.aligned.m8n8.x2.shared.b16 {%0,%1}, [%2];"
                 : "=r"(b[0]), "=r"(b[1]) : "r"(addr));
}
__device__ __forceinline__ void ldmBT(uint32_t b[2], uint32_t addr) {
    asm volatile("ldmatrix.sync.aligned.m8n8.x2.trans.shared.b16 {%0,%1}, [%2];"
                 : "=r"(b[0]), "=r"(b[1]) : "r"(addr));
}
__device__ __forceinline__ void mma16816(float d[4], const uint32_t a[4],
                                         const uint32_t b[2]) {
    asm volatile(
        "mma.sync.aligned.m16n8k16.row.col.f32.bf16.bf16.f32 "
        "{%0,%1,%2,%3}, {%4,%5,%6,%7}, {%8,%9}, {%0,%1,%2,%3};"
        : "+f"(d[0]), "+f"(d[1]), "+f"(d[2]), "+f"(d[3])
        : "r"(a[0]), "r"(a[1]), "r"(a[2]), "r"(a[3]), "r"(b[0]), "r"(b[1]));
}
__device__ __forceinline__ void cvt_pair(float a, float b, uint32_t& hi, uint32_t& lo) {
    __nv_bfloat162 h = __floats2bfloat162_rn(a, b);
    float2 hf = __bfloat1622float2(h);
    __nv_bfloat162 l = __floats2bfloat162_rn(a - hf.x, b - hf.y);
    hi = *(uint32_t*)&h;
    lo = *(uint32_t*)&l;
}
__device__ __forceinline__ void pf_l1(const float* p) {
    asm volatile("prefetch.global.L1 [%0];" :: "l"(p));
}

__global__ void __launch_bounds__(256, 2)
fast_attn_hmma(const float* __restrict__ q, const float* __restrict__ k,
               const float* __restrict__ v, const float* __restrict__ rpe,
               float* __restrict__ out)
{
    extern __shared__ __align__(1024) char smc[];
    const uint32_t sb = smem_u32(smc);
    float* Pring = (float*)(smc + RING);
    // denominators live in the ring's slack column (slot 128 of each row)
    #define DSM(i) Pring[(i) * RSTR + 128]

    const int bh = blockIdx.y;
    const int i0 = blockIdx.x * BI;
    const int t = threadIdx.x, lane = t & 31, w = t >> 5;
    const int wi = w >> 2, wj = w & 3;   // warp: rows wi*32..+31, j-cols wj*16..+15
    const int qr = lane >> 2, qc = (lane & 3) * 2;

    const uint32_t xl   = (uint32_t)(lane & 7) << 4;
    const uint32_t xs   = (uint32_t)qr << 4;
    const uint32_t aoff = ((uint32_t)((lane & 7) + (lane & 8)) << 7) |
                          (((uint32_t)(lane >> 4) & 1) << 4);
    const uint32_t boff = ((uint32_t)(lane & 7) << 7) |
                          (((uint32_t)(lane >> 3) & 1) << 4);
    const uint32_t voff = (uint32_t)(lane & 15) << 7;

    const float* qb = q + (size_t)bh * NSEQ * 64;
    const float* kb = k + (size_t)bh * NSEQ * 64;
    const float* vb = v + (size_t)bh * NSEQ * 64;

    // ---- convert Q tile once (64x64 -> bf16 hi/lo) ----
    #pragma unroll
    for (int it = 0; it < 4; ++it) {
        int e = t + it * 256;
        int row = e >> 4, c4 = e & 15;
        float4 x = *(const float4*)(qb + (size_t)(i0 + row) * 64 + c4 * 4);
        uint32_t h0, l0, h1, l1;
        cvt_pair(x.x, x.y, h0, l0);
        cvt_pair(x.z, x.w, h1, l1);
        uint32_t sw = SWZ((uint32_t)(row * 128 + c4 * 8));
        *(uint2*)(smc + Q_HI + sw) = make_uint2(h0, h1);
        *(uint2*)(smc + Q_LO + sw) = make_uint2(l0, l1);
    }
    if (t < 64) DSM(t) = 0.f;
    __syncthreads();

    // ---- preload Q_HI A-fragments (tile-invariant) ----
    uint32_t qA[2][4][4];
    #pragma unroll
    for (int mt = 0; mt < 2; ++mt)
        #pragma unroll
        for (int kk = 0; kk < 4; ++kk)
            ldmA(qA[mt][kk], sb + Q_HI +
                 ((((uint32_t)(wi*32 + mt*16) << 7) + aoff + kk*32) ^ xl));

    // band MMA + ring stage for the R currently in smem (window base ustart)
    auto band_stage = [&](int ustart) {
        float bacc[2][2][4];
        #pragma unroll
        for (int a = 0; a < 2; ++a)
            #pragma unroll
            for (int b = 0; b < 2; ++b)
                #pragma unroll
                for (int r = 0; r < 4; ++r) bacc[a][b][r] = 0.f;
        #pragma unroll
        for (int p = 0; p < 2; ++p) {
            uint32_t Bb = (p == 0) ? R_HI : R_LO;
            #pragma unroll
            for (int kk = 0; kk < 4; ++kk) {
                uint32_t B[2][2];
                #pragma unroll
                for (int nt = 0; nt < 2; ++nt)
                    ldmB(B[nt], sb + Bb +
                         ((((uint32_t)(wj*16 + nt*8) << 7) + boff + kk*32) ^ xl));
                #pragma unroll
                for (int mt = 0; mt < 2; ++mt)
                    #pragma unroll
                    for (int nt = 0; nt < 2; ++nt)
                        mma16816(bacc[mt][nt], qA[mt][kk], B[nt]);
            }
        }
        #pragma unroll
        for (int kk = 0; kk < 4; ++kk) {   // Q_LO x R_HI
            uint32_t A[2][4], B[2][2];
            #pragma unroll
            for (int mt = 0; mt < 2; ++mt)
                ldmA(A[mt], sb + Q_LO +
                     ((((uint32_t)(wi*32 + mt*16) << 7) + aoff + kk*32) ^ xl));
            #pragma unroll
            for (int nt = 0; nt < 2; ++nt)
                ldmB(B[nt], sb + R_HI +
                     ((((uint32_t)(wj*16 + nt*8) << 7) + boff + kk*32) ^ xl));
            #pragma unroll
            for (int mt = 0; mt < 2; ++mt)
                #pragma unroll
                for (int nt = 0; nt < 2; ++nt)
                    mma16816(bacc[mt][nt], A[mt], B[nt]);
        }
        const int base_s = ustart & 127;   // ustart multiple of 64 -> {0,64}
        #pragma unroll
        for (int mt = 0; mt < 2; ++mt)
            #pragma unroll
            for (int nt = 0; nt < 2; ++nt) {
                int row = wi*32 + mt*16 + qr;
                int slot = base_s + wj*16 + nt*8 + qc;
                *(float2*)&Pring[row * RSTR + slot] =
                    make_float2(bacc[mt][nt][0], bacc[mt][nt][1]);
                *(float2*)&Pring[(row + 8) * RSTR + slot] =
                    make_float2(bacc[mt][nt][2], bacc[mt][nt][3]);
            }
    };

    float oacc[2][2][4];
    float dsum[4];
    #pragma unroll
    for (int a = 0; a < 2; ++a)
        #pragma unroll
        for (int b = 0; b < 2; ++b)
            #pragma unroll
            for (int r = 0; r < 4; ++r) oacc[a][b][r] = 0.f;
    #pragma unroll
    for (int u = 0; u < 4; ++u) dsum[u] = 0.f;

    for (int tile = 0; tile < NT; ++tile) {
        const int j0 = tile * BJ;
        __syncthreads();   // full: prev SV done with S/V; K/V/R writable

        // ---- convert K tile ----
        #pragma unroll
        for (int it = 0; it < 4; ++it) {
            int e = t + it * 256;
            int row = e >> 4, c4 = e & 15;
            float4 x = *(const float4*)(kb + (size_t)(j0 + row) * 64 + c4 * 4);
            uint32_t h0, l0, h1, l1;
            cvt_pair(x.x, x.y, h0, l0);
            cvt_pair(x.z, x.w, h1, l1);
            uint32_t sw = SWZ((uint32_t)(row * 128 + c4 * 8));
            *(uint2*)(smc + K_HI + sw) = make_uint2(h0, h1);
            *(uint2*)(smc + K_LO + sw) = make_uint2(l0, l1);
        }
        // ---- convert V tile (natural [j][d]) ----
        #pragma unroll
        for (int it = 0; it < 4; ++it) {
            int e = t + it * 256;
            int row = e >> 4, c4 = e & 15;
            float4 x = *(const float4*)(vb + (size_t)(j0 + row) * 64 + c4 * 4);
            uint32_t h0, l0, h1, l1;
            cvt_pair(x.x, x.y, h0, l0);
            cvt_pair(x.z, x.w, h1, l1);
            uint32_t sw = SWZ((uint32_t)(row * 128 + c4 * 8));
            *(uint2*)(smc + V_HI + sw) = make_uint2(h0, h1);
            *(uint2*)(smc + V_LO + sw) = make_uint2(l0, l1);
        }

        // ---- band ring: new u-columns (2 groups at tile 0, else 1) ----
        const int ngroups = (tile == 0) ? 2 : 1;
        for (int g = 0; g < ngroups; ++g) {
            const int ustart = i0 + (NSEQ - BJ - BI + 1 + 63) - 64 * tile + 64 * g; // i0+960-64t+64g
            #pragma unroll
            for (int it = 0; it < 4; ++it) {
                int e = t + it * 256;
                int row = e >> 4, c4 = e & 15;
                int gr = ustart + row; if (gr > 2046) gr = 2046;
                float4 x = *(const float4*)(rpe + (size_t)gr * 64 + c4 * 4);
                uint32_t h0, l0, h1, l1;
                cvt_pair(x.x, x.y, h0, l0);
                cvt_pair(x.z, x.w, h1, l1);
                uint32_t sw = SWZ((uint32_t)(row * 128 + c4 * 8));
                *(uint2*)(smc + R_HI + sw) = make_uint2(h0, h1);
                *(uint2*)(smc + R_LO + sw) = make_uint2(l0, l1);
            }
            __syncthreads();   // full: R (and K/V on g=0) visible to all warps
            band_stage(ustart);
            if (g < ngroups - 1) __syncthreads();   // R reused by next group
        }

        // ---- QK MMAs (overlap ring-STS drain): zacc = Q K^T (3-split) ----
        float zacc[2][2][4];
        #pragma unroll
        for (int a = 0; a < 2; ++a)
            #pragma unroll
            for (int b = 0; b < 2; ++b)
                #pragma unroll
                for (int r = 0; r < 4; ++r) zacc[a][b][r] = 0.f;
        #pragma unroll
        for (int p = 0; p < 2; ++p) {
            uint32_t Bb = (p == 0) ? K_HI : K_LO;
            #pragma unroll
            for (int kk = 0; kk < 4; ++kk) {
                uint32_t B[2][2];
                #pragma unroll
                for (int nt = 0; nt < 2; ++nt)
                    ldmB(B[nt], sb + Bb +
                         ((((uint32_t)(wj*16 + nt*8) << 7) + boff + kk*32) ^ xl));
                #pragma unroll
                for (int mt = 0; mt < 2; ++mt)
                    #pragma unroll
                    for (int nt = 0; nt < 2; ++nt)
                        mma16816(zacc[mt][nt], qA[mt][kk], B[nt]);
            }
        }
        #pragma unroll
        for (int kk = 0; kk < 4; ++kk) {   // Q_LO x K_HI
            uint32_t A[2][4], B[2][2];
            #pragma unroll
            for (int mt = 0; mt < 2; ++mt)
                ldmA(A[mt], sb + Q_LO +
                     ((((uint32_t)(wi*32 + mt*16) << 7) + aoff + kk*32) ^ xl));
            #pragma unroll
            for (int nt = 0; nt < 2; ++nt)
                ldmB(B[nt], sb + K_HI +
                     ((((uint32_t)(wj*16 + nt*8) << 7) + boff + kk*32) ^ xl));
            #pragma unroll
            for (int mt = 0; mt < 2; ++mt)
                #pragma unroll
                for (int nt = 0; nt < 2; ++nt)
                    mma16816(zacc[mt][nt], A[mt], B[nt]);
        }
        named_bar(1 + wi);   // A (per-wi): ring rows for this wi staged

        // ---- gather band from ring; s-transform; S store ----
        {
            int gb = (i0 - 64 * tile + 1023) & 127;   // in {63,127}
            #pragma unroll
            for (int mt = 0; mt < 2; ++mt)
                #pragma unroll
                for (int nt = 0; nt < 2; ++nt)
                    #pragma unroll
                    for (int r = 0; r < 4; ++r) {
                        int ii = wi*32 + mt*16 + qr + ((r >> 1) << 3);
                        int jj = wj*16 + nt*8 + qc + (r & 1);
                        int slot = gb + ii - jj;        // >= 0 since gb >= 63
                        if (slot >= 128) slot -= 128;
                        zacc[mt][nt][r] += Pring[ii * RSTR + slot];
                    }
        }
        #pragma unroll
        for (int mt = 0; mt < 2; ++mt)
            #pragma unroll
            for (int nt = 0; nt < 2; ++nt)
                #pragma unroll
                for (int r = 0; r < 4; ++r) {
                    float z = zacc[mt][nt][r];
                    float s = fmaf(z, fmaf(z, 0.5f, 1.f), 1.f);
                    zacc[mt][nt][r] = s;
                    dsum[mt * 2 + (r >> 1)] += s;
                }
        #pragma unroll
        for (int mt = 0; mt < 2; ++mt)
            #pragma unroll
            for (int nt = 0; nt < 2; ++nt) {
                int r0 = wi*32 + mt*16 + qr;
                int c0 = wj*16 + nt*8 + qc;
                uint32_t h0, l0, h1, l1;
                cvt_pair(zacc[mt][nt][0], zacc[mt][nt][1], h0, l0);
                cvt_pair(zacc[mt][nt][2], zacc[mt][nt][3], h1, l1);
                uint32_t off0 = ((uint32_t)(r0 * 128 + c0 * 2)) ^ xs;
                *(uint32_t*)(smc + S_HI + off0) = h0;
                *(uint32_t*)(smc + S_LO + off0) = l0;
                *(uint32_t*)(smc + S_HI + off0 + 1024) = h1;
                *(uint32_t*)(smc + S_LO + off0 + 1024) = l1;
            }
        named_bar(1 + wi);   // B (per-wi): this wi's S rows visible

        // ---- L1 prefetch hints for tile t+1 ----
        if (tile < NT - 1 && (t & 3) == 0) {
            int row = t >> 2;   // 0..63
            const float* kp = kb + (size_t)(j0 + 64) * 64;
            const float* vp = vb + (size_t)(j0 + 64) * 64;
            int un = i0 + 960 - 64 * (tile + 1);
            pf_l1(kp + (size_t)row * 64);
            pf_l1(kp + (size_t)row * 64 + 32);
            pf_l1(vp + (size_t)row * 64);
            pf_l1(vp + (size_t)row * 64 + 32);
            int g0 = un + row; if (g0 > 2046) g0 = 2046;
            pf_l1(rpe + (size_t)g0 * 64);
            pf_l1(rpe + (size_t)g0 * 64 + 32);
        }

        // ---- SV MMAs: O += S V (3-split; vB cached) ----
        {
            uint32_t vB[4][2][2];
            #pragma unroll
            for (int kk = 0; kk < 4; ++kk)
                #pragma unroll
                for (int nt = 0; nt < 2; ++nt)
                    ldmBT(vB[kk][nt], sb + V_HI +
                          ((((uint32_t)(kk*16) << 7) + voff +
                            (uint32_t)(wj*32 + nt*16)) ^ xl));
            #pragma unroll
            for (int kk = 0; kk < 4; ++kk) {
                uint32_t A[2][4];
                #pragma unroll
                for (int mt = 0; mt < 2; ++mt)
                    ldmA(A[mt], sb + S_HI +
                         ((((uint32_t)(wi*32 + mt*16) << 7) + aoff + kk*32) ^ xl));
                #pragma unroll
                for (int mt = 0; mt < 2; ++mt)     // S_HI x V_HI
                    #pragma unroll
                    for (int nt = 0; nt < 2; ++nt)
                        mma16816(oacc[mt][nt], A[mt], vB[kk][nt]);
                uint32_t B[2][2];
                #pragma unroll
                for (int nt = 0; nt < 2; ++nt)
                    ldmBT(B[nt], sb + V_LO +
                          ((((uint32_t)(kk*16) << 7) + voff +
                            (uint32_t)(wj*32 + nt*16)) ^ xl));
                #pragma unroll
                for (int mt = 0; mt < 2; ++mt)     // S_HI x V_LO
                    #pragma unroll
                    for (int nt = 0; nt < 2; ++nt)
                        mma16816(oacc[mt][nt], A[mt], B[nt]);
                uint32_t A2[2][4];
                #pragma unroll
                for (int mt = 0; mt < 2; ++mt)
                    ldmA(A2[mt], sb + S_LO +
                         ((((uint32_t)(wi*32 + mt*16) << 7) + aoff + kk*32) ^ xl));
                #pragma unroll
                for (int mt = 0; mt < 2; ++mt)     // S_LO x V_HI
                    #pragma unroll
                    for (int nt = 0; nt < 2; ++nt)
                        mma16816(oacc[mt][nt], A2[mt], vB[kk][nt]);
            }
        }
    }

    // ---- reduce denominators ----
    #pragma unroll
    for (int u = 0; u < 4; ++u) {
        float s = dsum[u];
        s += __shfl_xor_sync(0xffffffffu, s, 1);
        s += __shfl_xor_sync(0xffffffffu, s, 2);
        if ((lane & 3) == 0)
            atomicAdd(&DSM(wi*32 + (u >> 1)*16 + qr + ((u & 1) << 3)), s);
    }
    __syncthreads();

    // ---- epilogue ----
    #pragma unroll
    for (int mt = 0; mt < 2; ++mt)
        #pragma unroll
        for (int nt = 0; nt < 2; ++nt) {
            int ii = wi*32 + mt*16 + qr;
            int d0 = wj*16 + nt*8 + qc;
            float inv0 = 1.f / DSM(ii);
            float inv1 = 1.f / DSM(ii + 8);
            float* o0 = out + ((size_t)(bh * NSEQ + i0 + ii)) * 64 + d0;
            *(float2*)o0 = make_float2(oacc[mt][nt][0] * inv0, oacc[mt][nt][1] * inv0);
            *(float2*)(o0 + 8 * 64) =
                make_float2(oacc[mt][nt][2] * inv1, oacc[mt][nt][3] * inv1);
        }
}

extern "C" void kernel_launch(void* const* d_in, const int* in_sizes, int n_in,
                              void* d_out, int out_size)
{
    const float* q   = (const float*)d_in[0];
    const float* k   = (const float*)d_in[1];
    const float* v   = (const float*)d_in[2];
    // d_in[3] = drop_noise (unused)
    const float* rpe = (const float*)d_in[4];
    float* out = (float*)d_out;

    cudaFuncSetAttribute(fast_attn_hmma,
                         cudaFuncAttributeMaxDynamicSharedMemorySize, SMEM_BYTES);
    dim3 grid(NSEQ / BI, 16);   // 16 x 16 = 256 CTAs -> 2 per SM
    fast_attn_hmma<<<grid, 256, SMEM_BYTES>>>(q, k, v, rpe, out);
}

// round 15
// speedup vs baseline: 1.0824x; 1.0824x over previous
#include <cuda_runtime.h>
#include <cuda_bf16.h>
#include <cstdint>

// Degree-2 Taylor attention with RPE via warp-level mma.sync (bf16 x3-split)
// + rolling band ring + L1/L2 prefetch + per-wi named barriers
// + in-register S fragments for the warp's own k-block in SV.
// BI=128, BJ=64, 512 threads (16 warps), grid 8 x 16 = 128 CTAs, 1 CTA/SM.

constexpr int NSEQ = 1024, BI = 128, BJ = 64, NT = NSEQ / BJ;
constexpr int RSTR = 200;   // ring stride in floats

// smem byte offsets
constexpr int Q_HI = 0,      Q_LO = 16384;   // 128x64 bf16
constexpr int K_HI = 32768,  K_LO = 40960;   // 64x64
constexpr int R_HI = 49152,  R_LO = 57344;   // 64 rpe rows
constexpr int V_HI = 65536,  V_LO = 73728;   // 64x64 natural
constexpr int S_HI = 81920,  S_LO = 98304;   // 128x64
constexpr int RING = 114688;                 // 128 x 200 f32 ring
constexpr int DEN  = RING + 128 * RSTR * 4;  // 217088
constexpr int SMEM_BYTES = DEN + 512;        // 217600

#define SWZ(o) ((o) ^ ((((o) >> 7) & 7) << 4))

__device__ __forceinline__ uint32_t smem_u32(const void* p) {
    uint32_t a;
    asm("{ .reg .u64 t; cvta.to.shared.u64 t, %1; cvt.u32.u64 %0, t; }"
        : "=r"(a) : "l"(p));
    return a;
}
__device__ __forceinline__ void named_bar(int id) {
    asm volatile("bar.sync %0, 128;" :: "r"(id) : "memory");
}
__device__ __forceinline__ void ldmA(uint32_t a[4], uint32_t addr) {
    asm volatile("ldmatrix.sync.aligned.m8n8.x4.shared.b16 {%0,%1,%2,%3}, [%4];"
                 : "=r"(a[0]), "=r"(a[1]), "=r"(a[2]), "=r"(a[3]) : "r"(addr));
}
__device__ __forceinline__ void ldmB(uint32_t b[2], uint32_t addr) {
    asm volatile("ldmatrix.sync.aligned.m8n8.x2.shared.b16 {%0,%1}, [%2];"
                 : "=r"(b[0]), "=r"(b[1]) : "r"(addr));
}
__device__ __forceinline__ void ldmBT(uint32_t b[2], uint32_t addr) {
    asm volatile("ldmatrix.sync.aligned.m8n8.x2.trans.shared.b16 {%0,%1}, [%2];"
                 : "=r"(b[0]), "=r"(b[1]) : "r"(addr));
}
__device__ __forceinline__ void mma16816(float d[4], const uint32_t a[4],
                                         const uint32_t b[2]) {
    asm volatile(
        "mma.sync.aligned.m16n8k16.row.col.f32.bf16.bf16.f32 "
        "{%0,%1,%2,%3}, {%4,%5,%6,%7}, {%8,%9}, {%0,%1,%2,%3};"
        : "+f"(d[0]), "+f"(d[1]), "+f"(d[2]), "+f"(d[3])
        : "r"(a[0]), "r"(a[1]), "r"(a[2]), "r"(a[3]), "r"(b[0]), "r"(b[1]));
}
__device__ __forceinline__ void cvt_pair(float a, float b, uint32_t& hi, uint32_t& lo) {
    __nv_bfloat162 h = __floats2bfloat162_rn(a, b);
    float2 hf = __bfloat1622float2(h);
    __nv_bfloat162 l = __floats2bfloat162_rn(a - hf.x, b - hf.y);
    hi = *(uint32_t*)&h;
    lo = *(uint32_t*)&l;
}
__device__ __forceinline__ void pf_l1(const float* p) {
    asm volatile("prefetch.global.L1 [%0];" :: "l"(p));
}
__device__ __forceinline__ void pf_l2(const float* p) {
    asm volatile("prefetch.global.L2 [%0];" :: "l"(p));
}

__global__ void __launch_bounds__(512, 1)
fast_attn_hmma(const float* __restrict__ q, const float* __restrict__ k,
               const float* __restrict__ v, const float* __restrict__ rpe,
               float* __restrict__ out)
{
    extern __shared__ __align__(1024) char smc[];
    const uint32_t sb = smem_u32(smc);
    float* Pring = (float*)(smc + RING);
    float* Dsm = (float*)(smc + DEN);

    const int bh = blockIdx.y;
    const int i0 = blockIdx.x * BI;
    const int t = threadIdx.x, lane = t & 31, w = t >> 5;
    const int wi = w >> 2, wj = w & 3;   // warp: rows wi*32..+31, j-cols wj*16..+15
    const int qr = lane >> 2, qc = (lane & 3) * 2;

    const uint32_t xl   = (uint32_t)(lane & 7) << 4;
    const uint32_t xs   = (uint32_t)qr << 4;
    const uint32_t aoff = ((uint32_t)((lane & 7) + (lane & 8)) << 7) |
                          (((uint32_t)(lane >> 4) & 1) << 4);
    const uint32_t boff = ((uint32_t)(lane & 7) << 7) |
                          (((uint32_t)(lane >> 3) & 1) << 4);
    const uint32_t voff = (uint32_t)(lane & 15) << 7;

    const float* qb = q + (size_t)bh * NSEQ * 64;
    const float* kb = k + (size_t)bh * NSEQ * 64;
    const float* vb = v + (size_t)bh * NSEQ * 64;

    // ---- convert Q tile once (128x64 -> bf16 hi/lo) ----
    #pragma unroll
    for (int it = 0; it < 4; ++it) {
        int e = t + it * 512;
        int row = e >> 4, c4 = e & 15;
        float4 x = *(const float4*)(qb + (size_t)(i0 + row) * 64 + c4 * 4);
        uint32_t h0, l0, h1, l1;
        cvt_pair(x.x, x.y, h0, l0);
        cvt_pair(x.z, x.w, h1, l1);
        uint32_t sw = SWZ((uint32_t)(row * 128 + c4 * 8));
        *(uint2*)(smc + Q_HI + sw) = make_uint2(h0, h1);
        *(uint2*)(smc + Q_LO + sw) = make_uint2(l0, l1);
    }
    if (t < 128) Dsm[t] = 0.f;
    __syncthreads();

    // ---- preload Q_HI A-fragments (tile-invariant) ----
    uint32_t qA[2][4][4];
    #pragma unroll
    for (int mt = 0; mt < 2; ++mt)
        #pragma unroll
        for (int kk = 0; kk < 4; ++kk)
            ldmA(qA[mt][kk], sb + Q_HI +
                 ((((uint32_t)(wi*32 + mt*16) << 7) + aoff + kk*32) ^ xl));

    // band MMA + ring stage for the R currently in smem (window base ustart)
    auto band_stage = [&](int ustart) {
        float bacc[2][2][4];
        #pragma unroll
        for (int a = 0; a < 2; ++a)
            #pragma unroll
            for (int b = 0; b < 2; ++b)
                #pragma unroll
                for (int r = 0; r < 4; ++r) bacc[a][b][r] = 0.f;
        #pragma unroll
        for (int p = 0; p < 2; ++p) {
            uint32_t Bb = (p == 0) ? R_HI : R_LO;
            #pragma unroll
            for (int kk = 0; kk < 4; ++kk) {
                uint32_t B[2][2];
                #pragma unroll
                for (int nt = 0; nt < 2; ++nt)
                    ldmB(B[nt], sb + Bb +
                         ((((uint32_t)(wj*16 + nt*8) << 7) + boff + kk*32) ^ xl));
                #pragma unroll
                for (int mt = 0; mt < 2; ++mt)
                    #pragma unroll
                    for (int nt = 0; nt < 2; ++nt)
                        mma16816(bacc[mt][nt], qA[mt][kk], B[nt]);
            }
        }
        #pragma unroll
        for (int kk = 0; kk < 4; ++kk) {   // Q_LO x R_HI
            uint32_t A[2][4], B[2][2];
            #pragma unroll
            for (int mt = 0; mt < 2; ++mt)
                ldmA(A[mt], sb + Q_LO +
                     ((((uint32_t)(wi*32 + mt*16) << 7) + aoff + kk*32) ^ xl));
            #pragma unroll
            for (int nt = 0; nt < 2; ++nt)
                ldmB(B[nt], sb + R_HI +
                     ((((uint32_t)(wj*16 + nt*8) << 7) + boff + kk*32) ^ xl));
            #pragma unroll
            for (int mt = 0; mt < 2; ++mt)
                #pragma unroll
                for (int nt = 0; nt < 2; ++nt)
                    mma16816(bacc[mt][nt], A[mt], B[nt]);
        }
        const int base_s = ustart % 192;
        #pragma unroll
        for (int mt = 0; mt < 2; ++mt)
            #pragma unroll
            for (int nt = 0; nt < 2; ++nt) {
                int row = wi*32 + mt*16 + qr;
                int slot = base_s + wj*16 + nt*8 + qc;
                *(float2*)&Pring[row * RSTR + slot] =
                    make_float2(bacc[mt][nt][0], bacc[mt][nt][1]);
                *(float2*)&Pring[(row + 8) * RSTR + slot] =
                    make_float2(bacc[mt][nt][2], bacc[mt][nt][3]);
            }
    };

    float oacc[2][2][4];
    float dsum[4];
    #pragma unroll
    for (int a = 0; a < 2; ++a)
        #pragma unroll
        for (int b = 0; b < 2; ++b)
            #pragma unroll
            for (int r = 0; r < 4; ++r) oacc[a][b][r] = 0.f;
    #pragma unroll
    for (int u = 0; u < 4; ++u) dsum[u] = 0.f;

    for (int tile = 0; tile < NT; ++tile) {
        const int j0 = tile * BJ;
        __syncthreads();   // full: prev SV done with S/V; K/V/R writable

        // ---- convert K tile ----
        #pragma unroll
        for (int it = 0; it < 2; ++it) {
            int e = t + it * 512;
            int row = e >> 4, c4 = e & 15;
            float4 x = *(const float4*)(kb + (size_t)(j0 + row) * 64 + c4 * 4);
            uint32_t h0, l0, h1, l1;
            cvt_pair(x.x, x.y, h0, l0);
            cvt_pair(x.z, x.w, h1, l1);
            uint32_t sw = SWZ((uint32_t)(row * 128 + c4 * 8));
            *(uint2*)(smc + K_HI + sw) = make_uint2(h0, h1);
            *(uint2*)(smc + K_LO + sw) = make_uint2(l0, l1);
        }
        // ---- convert V tile (natural [j][d]) ----
        #pragma unroll
        for (int it = 0; it < 2; ++it) {
            int e = t + it * 512;
            int row = e >> 4, c4 = e & 15;
            float4 x = *(const float4*)(vb + (size_t)(j0 + row) * 64 + c4 * 4);
            uint32_t h0, l0, h1, l1;
            cvt_pair(x.x, x.y, h0, l0);
            cvt_pair(x.z, x.w, h1, l1);
            uint32_t sw = SWZ((uint32_t)(row * 128 + c4 * 8));
            *(uint2*)(smc + V_HI + sw) = make_uint2(h0, h1);
            *(uint2*)(smc + V_LO + sw) = make_uint2(l0, l1);
        }

        // ---- band ring: new u-columns (3 groups at tile 0, else 1) ----
        const int ngroups = (tile == 0) ? 3 : 1;
        for (int g = 0; g < ngroups; ++g) {
            const int ustart = i0 + 960 - 64 * tile + 64 * g;
            #pragma unroll
            for (int it = 0; it < 2; ++it) {
                int e = t + it * 512;
                int row = e >> 4, c4 = e & 15;
                int gr = ustart + row; if (gr > 2046) gr = 2046;
                float4 x = *(const float4*)(rpe + (size_t)gr * 64 + c4 * 4);
                uint32_t h0, l0, h1, l1;
                cvt_pair(x.x, x.y, h0, l0);
                cvt_pair(x.z, x.w, h1, l1);
                uint32_t sw = SWZ((uint32_t)(row * 128 + c4 * 8));
                *(uint2*)(smc + R_HI + sw) = make_uint2(h0, h1);
                *(uint2*)(smc + R_LO + sw) = make_uint2(l0, l1);
            }
            __syncthreads();   // full: R (and K/V on g=0) visible to all warps
            band_stage(ustart);
            if (g < ngroups - 1) __syncthreads();   // R reused by next group
        }

        // ---- QK MMAs (overlap ring-STS drain): zacc = Q K^T (3-split) ----
        float zacc[2][2][4];
        #pragma unroll
        for (int a = 0; a < 2; ++a)
            #pragma unroll
            for (int b = 0; b < 2; ++b)
                #pragma unroll
                for (int r = 0; r < 4; ++r) zacc[a][b][r] = 0.f;
        #pragma unroll
        for (int p = 0; p < 2; ++p) {
            uint32_t Bb = (p == 0) ? K_HI : K_LO;
            #pragma unroll
            for (int kk = 0; kk < 4; ++kk) {
                uint32_t B[2][2];
                #pragma unroll
                for (int nt = 0; nt < 2; ++nt)
                    ldmB(B[nt], sb + Bb +
                         ((((uint32_t)(wj*16 + nt*8) << 7) + boff + kk*32) ^ xl));
                #pragma unroll
                for (int mt = 0; mt < 2; ++mt)
                    #pragma unroll
                    for (int nt = 0; nt < 2; ++nt)
                        mma16816(zacc[mt][nt], qA[mt][kk], B[nt]);
            }
        }
        #pragma unroll
        for (int kk = 0; kk < 4; ++kk) {   // Q_LO x K_HI
            uint32_t A[2][4], B[2][2];
            #pragma unroll
            for (int mt = 0; mt < 2; ++mt)
                ldmA(A[mt], sb + Q_LO +
                     ((((uint32_t)(wi*32 + mt*16) << 7) + aoff + kk*32) ^ xl));
            #pragma unroll
            for (int nt = 0; nt < 2; ++nt)
                ldmB(B[nt], sb + K_HI +
                     ((((uint32_t)(wj*16 + nt*8) << 7) + boff + kk*32) ^ xl));
            #pragma unroll
            for (int mt = 0; mt < 2; ++mt)
                #pragma unroll
                for (int nt = 0; nt < 2; ++nt)
                    mma16816(zacc[mt][nt], A[mt], B[nt]);
        }
        named_bar(1 + wi);   // A (per-wi): ring rows for this wi staged

        // ---- gather band from ring; s-transform; S store + keep own frags ----
        {
            int gb = (i0 - 64 * tile + 1023) % 192;
            #pragma unroll
            for (int mt = 0; mt < 2; ++mt)
                #pragma unroll
                for (int nt = 0; nt < 2; ++nt)
                    #pragma unroll
                    for (int r = 0; r < 4; ++r) {
                        int ii = wi*32 + mt*16 + qr + ((r >> 1) << 3);
                        int jj = wj*16 + nt*8 + qc + (r & 1);
                        int slot = gb + ii - jj;
                        if (slot >= 192) slot -= 192;
                        zacc[mt][nt][r] += Pring[ii * RSTR + slot];
                    }
        }
        uint32_t sHi[2][4], sLo[2][4];   // this warp's own SV A-frags (kk==wj)
        #pragma unroll
        for (int mt = 0; mt < 2; ++mt)
            #pragma unroll
            for (int nt = 0; nt < 2; ++nt)
                #pragma unroll
                for (int r = 0; r < 4; ++r) {
                    float z = zacc[mt][nt][r];
                    float s = fmaf(z, fmaf(z, 0.5f, 1.f), 1.f);
                    zacc[mt][nt][r] = s;
                    dsum[mt * 2 + (r >> 1)] += s;
                }
        #pragma unroll
        for (int mt = 0; mt < 2; ++mt)
            #pragma unroll
            for (int nt = 0; nt < 2; ++nt) {
                int r0 = wi*32 + mt*16 + qr;
                int c0 = wj*16 + nt*8 + qc;
                uint32_t h0, l0, h1, l1;
                cvt_pair(zacc[mt][nt][0], zacc[mt][nt][1], h0, l0);
                cvt_pair(zacc[mt][nt][2], zacc[mt][nt][3], h1, l1);
                sHi[mt][nt*2 + 0] = h0; sHi[mt][nt*2 + 1] = h1;
                sLo[mt][nt*2 + 0] = l0; sLo[mt][nt*2 + 1] = l1;
                uint32_t off0 = ((uint32_t)(r0 * 128 + c0 * 2)) ^ xs;
                *(uint32_t*)(smc + S_HI + off0) = h0;
                *(uint32_t*)(smc + S_LO + off0) = l0;
                *(uint32_t*)(smc + S_HI + off0 + 1024) = h1;
                *(uint32_t*)(smc + S_LO + off0 + 1024) = l1;
            }
        named_bar(1 + wi);   // B (per-wi): this wi's S rows visible

        // ---- prefetch: tile t+1 -> L1, tile t+2 -> L2 ----
        if (tile < NT - 1 && (t & 7) == 0) {
            int row = t >> 4;
            const float* kp = kb + (size_t)(j0 + 64) * 64;
            const float* vp = vb + (size_t)(j0 + 64) * 64;
            int un = i0 + 960 - 64 * (tile + 1);
            pf_l1(kp + (size_t)row * 64 + (t & 15) * 4);
            pf_l1(kp + (size_t)(row + 32) * 64 + (t & 15) * 4);
            pf_l1(vp + (size_t)row * 64 + (t & 15) * 4);
            pf_l1(vp + (size_t)(row + 32) * 64 + (t & 15) * 4);
            int g0 = un + row;      if (g0 > 2046) g0 = 2046;
            int g1 = un + row + 32; if (g1 > 2046) g1 = 2046;
            pf_l1(rpe + (size_t)g0 * 64 + (t & 15) * 4);
            pf_l1(rpe + (size_t)g1 * 64 + (t & 15) * 4);
            if (tile < NT - 2) {
                const float* kp2 = kb + (size_t)(j0 + 128) * 64;
                const float* vp2 = vb + (size_t)(j0 + 128) * 64;
                pf_l2(kp2 + (size_t)row * 64 + (t & 15) * 4);
                pf_l2(kp2 + (size_t)(row + 32) * 64 + (t & 15) * 4);
                pf_l2(vp2 + (size_t)row * 64 + (t & 15) * 4);
                pf_l2(vp2 + (size_t)(row + 32) * 64 + (t & 15) * 4);
            }
        }

        // ---- SV MMAs: O += S V (3-split; vB cached; own k-block from regs) ----
        {
            uint32_t vB[4][2][2];
            #pragma unroll
            for (int kk = 0; kk < 4; ++kk)
                #pragma unroll
                for (int nt = 0; nt < 2; ++nt)
                    ldmBT(vB[kk][nt], sb + V_HI +
                          ((((uint32_t)(kk*16) << 7) + voff +
                            (uint32_t)(wj*32 + nt*16)) ^ xl));
            #pragma unroll
            for (int kk = 0; kk < 4; ++kk) {
                uint32_t A[2][4];
                if (kk == wj) {
                    #pragma unroll
                    for (int mt = 0; mt < 2; ++mt)
                        #pragma unroll
                        for (int u = 0; u < 4; ++u) A[mt][u] = sHi[mt][u];
                } else {
                    #pragma unroll
                    for (int mt = 0; mt < 2; ++mt)
                        ldmA(A[mt], sb + S_HI +
                             ((((uint32_t)(wi*32 + mt*16) << 7) + aoff + kk*32) ^ xl));
                }
                #pragma unroll
                for (int mt = 0; mt < 2; ++mt)     // S_HI x V_HI
                    #pragma unroll
                    for (int nt = 0; nt < 2; ++nt)
                        mma16816(oacc[mt][nt], A[mt], vB[kk][nt]);
                uint32_t B[2][2];
                #pragma unroll
                for (int nt = 0; nt < 2; ++nt)
                    ldmBT(B[nt], sb + V_LO +
                          ((((uint32_t)(kk*16) << 7) + voff +
                            (uint32_t)(wj*32 + nt*16)) ^ xl));
                #pragma unroll
                for (int mt = 0; mt < 2; ++mt)     // S_HI x V_LO
                    #pragma unroll
                    for (int nt = 0; nt < 2; ++nt)
                        mma16816(oacc[mt][nt], A[mt], B[nt]);
                uint32_t A2[2][4];
                if (kk == wj) {
                    #pragma unroll
                    for (int mt = 0; mt < 2; ++mt)
                        #pragma unroll
                        for (int u = 0; u < 4; ++u) A2[mt][u] = sLo[mt][u];
                } else {
                    #pragma unroll
                    for (int mt = 0; mt < 2; ++mt)
                        ldmA(A2[mt], sb + S_LO +
                             ((((uint32_t)(wi*32 + mt*16) << 7) + aoff + kk*32) ^ xl));
                }
                #pragma unroll
                for (int mt = 0; mt < 2; ++mt)     // S_LO x V_HI
                    #pragma unroll
                    for (int nt = 0; nt < 2; ++nt)
                        mma16816(oacc[mt][nt], A2[mt], vB[kk][nt]);
            }
        }
    }

    // ---- reduce denominators ----
    #pragma unroll
    for (int u = 0; u < 4; ++u) {
        float s = dsum[u];
        s += __shfl_xor_sync(0xffffffffu, s, 1);
        s += __shfl_xor_sync(0xffffffffu, s, 2);
        if ((lane & 3) == 0)
            atomicAdd(&Dsm[wi*32 + (u >> 1)*16 + qr + ((u & 1) << 3)], s);
    }
    __syncthreads();

    // ---- epilogue ----
    #pragma unroll
    for (int mt = 0; mt < 2; ++mt)
        #pragma unroll
        for (int nt = 0; nt < 2; ++nt) {
            int ii = wi*32 + mt*16 + qr;
            int d0 = wj*16 + nt*8 + qc;
            float inv0 = 1.f / Dsm[ii];
            float inv1 = 1.f / Dsm[ii + 8];
            float* o0 = out + ((size_t)(bh * NSEQ + i0 + ii)) * 64 + d0;
            *(float2*)o0 = make_float2(oacc[mt][nt][0] * inv0, oacc[mt][nt][1] * inv0);
            *(float2*)(o0 + 8 * 64) =
                make_float2(oacc[mt][nt][2] * inv1, oacc[mt][nt][3] * inv1);
        }
}

extern "C" void kernel_launch(void* const* d_in, const int* in_sizes, int n_in,
                              void* d_out, int out_size)
{
    const float* q   = (const float*)d_in[0];
    const float* k   = (const float*)d_in[1];
    const float* v   = (const float*)d_in[2];
    // d_in[3] = drop_noise (unused)
    const float* rpe = (const float*)d_in[4];
    float* out = (float*)d_out;

    cudaFuncSetAttribute(fast_attn_hmma,
                         cudaFuncAttributeMaxDynamicSharedMemorySize, SMEM_BYTES);
    dim3 grid(NSEQ / BI, 16);   // 8 x 16 = 128 CTAs, one wave
    fast_attn_hmma<<<grid, 512, SMEM_BYTES>>>(q, k, v, rpe, out);
}

// round 16
// speedup vs baseline: 1.1762x; 1.0866x over previous
#include <cuda_runtime.h>
#include <cuda_bf16.h>
#include <cstdint>

// Degree-2 Taylor attention with RPE via warp-level mma.sync (bf16 x3-split)
// + rolling band ring + L1/L2 prefetch + per-wi-group named barriers.
// (R12 baseline + distance-2 L2 prefetch; zero register delta.)
// BI=128, BJ=64, 512 threads (16 warps), grid 8 x 16 = 128 CTAs, 1 CTA/SM.

constexpr int NSEQ = 1024, BI = 128, BJ = 64, NT = NSEQ / BJ;
constexpr int RSTR = 200;   // ring stride in floats

// smem byte offsets
constexpr int Q_HI = 0,      Q_LO = 16384;   // 128x64 bf16
constexpr int K_HI = 32768,  K_LO = 40960;   // 64x64
constexpr int R_HI = 49152,  R_LO = 57344;   // 64 rpe rows
constexpr int V_HI = 65536,  V_LO = 73728;   // 64x64 natural
constexpr int S_HI = 81920,  S_LO = 98304;   // 128x64
constexpr int RING = 114688;                 // 128 x 200 f32 ring
constexpr int DEN  = RING + 128 * RSTR * 4;  // 217088
constexpr int SMEM_BYTES = DEN + 512;        // 217600

#define SWZ(o) ((o) ^ ((((o) >> 7) & 7) << 4))

__device__ __forceinline__ uint32_t smem_u32(const void* p) {
    uint32_t a;
    asm("{ .reg .u64 t; cvta.to.shared.u64 t, %1; cvt.u32.u64 %0, t; }"
        : "=r"(a) : "l"(p));
    return a;
}
__device__ __forceinline__ void named_bar(int id) {
    asm volatile("bar.sync %0, 128;" :: "r"(id) : "memory");
}
__device__ __forceinline__ void ldmA(uint32_t a[4], uint32_t addr) {
    asm volatile("ldmatrix.sync.aligned.m8n8.x4.shared.b16 {%0,%1,%2,%3}, [%4];"
                 : "=r"(a[0]), "=r"(a[1]), "=r"(a[2]), "=r"(a[3]) : "r"(addr));
}
__device__ __forceinline__ void ldmB(uint32_t b[2], uint32_t addr) {
    asm volatile("ldmatrix.sync.aligned.m8n8.x2.shared.b16 {%0,%1}, [%2];"
                 : "=r"(b[0]), "=r"(b[1]) : "r"(addr));
}
__device__ __forceinline__ void ldmBT(uint32_t b[2], uint32_t addr) {
    asm volatile("ldmatrix.sync.aligned.m8n8.x2.trans.shared.b16 {%0,%1}, [%2];"
                 : "=r"(b[0]), "=r"(b[1]) : "r"(addr));
}
__device__ __forceinline__ void mma16816(float d[4], const uint32_t a[4],
                                         const uint32_t b[2]) {
    asm volatile(
        "mma.sync.aligned.m16n8k16.row.col.f32.bf16.bf16.f32 "
        "{%0,%1,%2,%3}, {%4,%5,%6,%7}, {%8,%9}, {%0,%1,%2,%3};"
        : "+f"(d[0]), "+f"(d[1]), "+f"(d[2]), "+f"(d[3])
        : "r"(a[0]), "r"(a[1]), "r"(a[2]), "r"(a[3]), "r"(b[0]), "r"(b[1]));
}
__device__ __forceinline__ void cvt_pair(float a, float b, uint32_t& hi, uint32_t& lo) {
    __nv_bfloat162 h = __floats2bfloat162_rn(a, b);
    float2 hf = __bfloat1622float2(h);
    __nv_bfloat162 l = __floats2bfloat162_rn(a - hf.x, b - hf.y);
    hi = *(uint32_t*)&h;
    lo = *(uint32_t*)&l;
}
__device__ __forceinline__ void pf_l1(const float* p) {
    asm volatile("prefetch.global.L1 [%0];" :: "l"(p));
}
__device__ __forceinline__ void pf_l2(const float* p) {
    asm volatile("prefetch.global.L2 [%0];" :: "l"(p));
}

__global__ void __launch_bounds__(512, 1)
fast_attn_hmma(const float* __restrict__ q, const float* __restrict__ k,
               const float* __restrict__ v, const float* __restrict__ rpe,
               float* __restrict__ out)
{
    extern __shared__ __align__(1024) char smc[];
    const uint32_t sb = smem_u32(smc);
    float* Pring = (float*)(smc + RING);
    float* Dsm = (float*)(smc + DEN);

    const int bh = blockIdx.y;
    const int i0 = blockIdx.x * BI;
    const int t = threadIdx.x, lane = t & 31, w = t >> 5;
    const int wi = w >> 2, wj = w & 3;   // warp: rows wi*32..+31, j-cols wj*16..+15
    const int qr = lane >> 2, qc = (lane & 3) * 2;

    const uint32_t xl   = (uint32_t)(lane & 7) << 4;
    const uint32_t xs   = (uint32_t)qr << 4;
    const uint32_t aoff = ((uint32_t)((lane & 7) + (lane & 8)) << 7) |
                          (((uint32_t)(lane >> 4) & 1) << 4);
    const uint32_t boff = ((uint32_t)(lane & 7) << 7) |
                          (((uint32_t)(lane >> 3) & 1) << 4);
    const uint32_t voff = (uint32_t)(lane & 15) << 7;

    const float* qb = q + (size_t)bh * NSEQ * 64;
    const float* kb = k + (size_t)bh * NSEQ * 64;
    const float* vb = v + (size_t)bh * NSEQ * 64;

    // ---- convert Q tile once (128x64 -> bf16 hi/lo) ----
    #pragma unroll
    for (int it = 0; it < 4; ++it) {
        int e = t + it * 512;
        int row = e >> 4, c4 = e & 15;
        float4 x = *(const float4*)(qb + (size_t)(i0 + row) * 64 + c4 * 4);
        uint32_t h0, l0, h1, l1;
        cvt_pair(x.x, x.y, h0, l0);
        cvt_pair(x.z, x.w, h1, l1);
        uint32_t sw = SWZ((uint32_t)(row * 128 + c4 * 8));
        *(uint2*)(smc + Q_HI + sw) = make_uint2(h0, h1);
        *(uint2*)(smc + Q_LO + sw) = make_uint2(l0, l1);
    }
    if (t < 128) Dsm[t] = 0.f;
    __syncthreads();

    // ---- preload Q_HI A-fragments (tile-invariant) ----
    uint32_t qA[2][4][4];
    #pragma unroll
    for (int mt = 0; mt < 2; ++mt)
        #pragma unroll
        for (int kk = 0; kk < 4; ++kk)
            ldmA(qA[mt][kk], sb + Q_HI +
                 ((((uint32_t)(wi*32 + mt*16) << 7) + aoff + kk*32) ^ xl));

    // band MMA + ring stage for the R currently in smem (window base ustart)
    auto band_stage = [&](int ustart) {
        float bacc[2][2][4];
        #pragma unroll
        for (int a = 0; a < 2; ++a)
            #pragma unroll
            for (int b = 0; b < 2; ++b)
                #pragma unroll
                for (int r = 0; r < 4; ++r) bacc[a][b][r] = 0.f;
        #pragma unroll
        for (int p = 0; p < 2; ++p) {
            uint32_t Bb = (p == 0) ? R_HI : R_LO;
            #pragma unroll
            for (int kk = 0; kk < 4; ++kk) {
                uint32_t B[2][2];
                #pragma unroll
                for (int nt = 0; nt < 2; ++nt)
                    ldmB(B[nt], sb + Bb +
                         ((((uint32_t)(wj*16 + nt*8) << 7) + boff + kk*32) ^ xl));
                #pragma unroll
                for (int mt = 0; mt < 2; ++mt)
                    #pragma unroll
                    for (int nt = 0; nt < 2; ++nt)
                        mma16816(bacc[mt][nt], qA[mt][kk], B[nt]);
            }
        }
        #pragma unroll
        for (int kk = 0; kk < 4; ++kk) {   // Q_LO x R_HI
            uint32_t A[2][4], B[2][2];
            #pragma unroll
            for (int mt = 0; mt < 2; ++mt)
                ldmA(A[mt], sb + Q_LO +
                     ((((uint32_t)(wi*32 + mt*16) << 7) + aoff + kk*32) ^ xl));
            #pragma unroll
            for (int nt = 0; nt < 2; ++nt)
                ldmB(B[nt], sb + R_HI +
                     ((((uint32_t)(wj*16 + nt*8) << 7) + boff + kk*32) ^ xl));
            #pragma unroll
            for (int mt = 0; mt < 2; ++mt)
                #pragma unroll
                for (int nt = 0; nt < 2; ++nt)
                    mma16816(bacc[mt][nt], A[mt], B[nt]);
        }
        const int base_s = ustart % 192;
        #pragma unroll
        for (int mt = 0; mt < 2; ++mt)
            #pragma unroll
            for (int nt = 0; nt < 2; ++nt) {
                int row = wi*32 + mt*16 + qr;
                int slot = base_s + wj*16 + nt*8 + qc;
                *(float2*)&Pring[row * RSTR + slot] =
                    make_float2(bacc[mt][nt][0], bacc[mt][nt][1]);
                *(float2*)&Pring[(row + 8) * RSTR + slot] =
                    make_float2(bacc[mt][nt][2], bacc[mt][nt][3]);
            }
    };

    float oacc[2][2][4];
    float dsum[4];
    #pragma unroll
    for (int a = 0; a < 2; ++a)
        #pragma unroll
        for (int b = 0; b < 2; ++b)
            #pragma unroll
            for (int r = 0; r < 4; ++r) oacc[a][b][r] = 0.f;
    #pragma unroll
    for (int u = 0; u < 4; ++u) dsum[u] = 0.f;

    for (int tile = 0; tile < NT; ++tile) {
        const int j0 = tile * BJ;
        __syncthreads();   // full: prev SV done with S/V; K/V/R writable

        // ---- convert K tile ----
        #pragma unroll
        for (int it = 0; it < 2; ++it) {
            int e = t + it * 512;
            int row = e >> 4, c4 = e & 15;
            float4 x = *(const float4*)(kb + (size_t)(j0 + row) * 64 + c4 * 4);
            uint32_t h0, l0, h1, l1;
            cvt_pair(x.x, x.y, h0, l0);
            cvt_pair(x.z, x.w, h1, l1);
            uint32_t sw = SWZ((uint32_t)(row * 128 + c4 * 8));
            *(uint2*)(smc + K_HI + sw) = make_uint2(h0, h1);
            *(uint2*)(smc + K_LO + sw) = make_uint2(l0, l1);
        }
        // ---- convert V tile (natural [j][d]) ----
        #pragma unroll
        for (int it = 0; it < 2; ++it) {
            int e = t + it * 512;
            int row = e >> 4, c4 = e & 15;
            float4 x = *(const float4*)(vb + (size_t)(j0 + row) * 64 + c4 * 4);
            uint32_t h0, l0, h1, l1;
            cvt_pair(x.x, x.y, h0, l0);
            cvt_pair(x.z, x.w, h1, l1);
            uint32_t sw = SWZ((uint32_t)(row * 128 + c4 * 8));
            *(uint2*)(smc + V_HI + sw) = make_uint2(h0, h1);
            *(uint2*)(smc + V_LO + sw) = make_uint2(l0, l1);
        }

        // ---- band ring: new u-columns (3 groups at tile 0, else 1) ----
        const int ngroups = (tile == 0) ? 3 : 1;
        for (int g = 0; g < ngroups; ++g) {
            const int ustart = i0 + 960 - 64 * tile + 64 * g;
            #pragma unroll
            for (int it = 0; it < 2; ++it) {
                int e = t + it * 512;
                int row = e >> 4, c4 = e & 15;
                int gr = ustart + row; if (gr > 2046) gr = 2046;
                float4 x = *(const float4*)(rpe + (size_t)gr * 64 + c4 * 4);
                uint32_t h0, l0, h1, l1;
                cvt_pair(x.x, x.y, h0, l0);
                cvt_pair(x.z, x.w, h1, l1);
                uint32_t sw = SWZ((uint32_t)(row * 128 + c4 * 8));
                *(uint2*)(smc + R_HI + sw) = make_uint2(h0, h1);
                *(uint2*)(smc + R_LO + sw) = make_uint2(l0, l1);
            }
            __syncthreads();   // full: R (and K/V on g=0) visible to all warps
            band_stage(ustart);
            if (g < ngroups - 1) __syncthreads();   // R reused by next group
        }

        // ---- QK MMAs (overlap ring-STS drain): zacc = Q K^T (3-split) ----
        float zacc[2][2][4];
        #pragma unroll
        for (int a = 0; a < 2; ++a)
            #pragma unroll
            for (int b = 0; b < 2; ++b)
                #pragma unroll
                for (int r = 0; r < 4; ++r) zacc[a][b][r] = 0.f;
        #pragma unroll
        for (int p = 0; p < 2; ++p) {
            uint32_t Bb = (p == 0) ? K_HI : K_LO;
            #pragma unroll
            for (int kk = 0; kk < 4; ++kk) {
                uint32_t B[2][2];
                #pragma unroll
                for (int nt = 0; nt < 2; ++nt)
                    ldmB(B[nt], sb + Bb +
                         ((((uint32_t)(wj*16 + nt*8) << 7) + boff + kk*32) ^ xl));
                #pragma unroll
                for (int mt = 0; mt < 2; ++mt)
                    #pragma unroll
                    for (int nt = 0; nt < 2; ++nt)
                        mma16816(zacc[mt][nt], qA[mt][kk], B[nt]);
            }
        }
        #pragma unroll
        for (int kk = 0; kk < 4; ++kk) {   // Q_LO x K_HI
            uint32_t A[2][4], B[2][2];
            #pragma unroll
            for (int mt = 0; mt < 2; ++mt)
                ldmA(A[mt], sb + Q_LO +
                     ((((uint32_t)(wi*32 + mt*16) << 7) + aoff + kk*32) ^ xl));
            #pragma unroll
            for (int nt = 0; nt < 2; ++nt)
                ldmB(B[nt], sb + K_HI +
                     ((((uint32_t)(wj*16 + nt*8) << 7) + boff + kk*32) ^ xl));
            #pragma unroll
            for (int mt = 0; mt < 2; ++mt)
                #pragma unroll
                for (int nt = 0; nt < 2; ++nt)
                    mma16816(zacc[mt][nt], A[mt], B[nt]);
        }
        named_bar(1 + wi);   // A (per-wi): ring rows for this wi staged

        // ---- gather band from ring; s-transform; S store ----
        {
            int gb = (i0 - 64 * tile + 1023) % 192;
            #pragma unroll
            for (int mt = 0; mt < 2; ++mt)
                #pragma unroll
                for (int nt = 0; nt < 2; ++nt)
                    #pragma unroll
                    for (int r = 0; r < 4; ++r) {
                        int ii = wi*32 + mt*16 + qr + ((r >> 1) << 3);
                        int jj = wj*16 + nt*8 + qc + (r & 1);
                        int slot = gb + ii - jj;
                        if (slot >= 192) slot -= 192;
                        zacc[mt][nt][r] += Pring[ii * RSTR + slot];
                    }
        }
        #pragma unroll
        for (int mt = 0; mt < 2; ++mt)
            #pragma unroll
            for (int nt = 0; nt < 2; ++nt)
                #pragma unroll
                for (int r = 0; r < 4; ++r) {
                    float z = zacc[mt][nt][r];
                    float s = fmaf(z, fmaf(z, 0.5f, 1.f), 1.f);
                    zacc[mt][nt][r] = s;
                    dsum[mt * 2 + (r >> 1)] += s;
                }
        #pragma unroll
        for (int mt = 0; mt < 2; ++mt)
            #pragma unroll
            for (int nt = 0; nt < 2; ++nt) {
                int r0 = wi*32 + mt*16 + qr;
                int c0 = wj*16 + nt*8 + qc;
                uint32_t h0, l0, h1, l1;
                cvt_pair(zacc[mt][nt][0], zacc[mt][nt][1], h0, l0);
                cvt_pair(zacc[mt][nt][2], zacc[mt][nt][3], h1, l1);
                uint32_t off0 = ((uint32_t)(r0 * 128 + c0 * 2)) ^ xs;
                *(uint32_t*)(smc + S_HI + off0) = h0;
                *(uint32_t*)(smc + S_LO + off0) = l0;
                *(uint32_t*)(smc + S_HI + off0 + 1024) = h1;
                *(uint32_t*)(smc + S_LO + off0 + 1024) = l1;
            }
        named_bar(1 + wi);   // B (per-wi): this wi's S rows visible

        // ---- prefetch: tile t+1 -> L1, K/V of tile t+2 -> L2 ----
        if (tile < NT - 1 && (t & 7) == 0) {
            int row = t >> 4;
            const float* kp = kb + (size_t)(j0 + 64) * 64;
            const float* vp = vb + (size_t)(j0 + 64) * 64;
            int un = i0 + 960 - 64 * (tile + 1);
            pf_l1(kp + (size_t)row * 64 + (t & 15) * 4);
            pf_l1(kp + (size_t)(row + 32) * 64 + (t & 15) * 4);
            pf_l1(vp + (size_t)row * 64 + (t & 15) * 4);
            pf_l1(vp + (size_t)(row + 32) * 64 + (t & 15) * 4);
            int g0 = un + row;      if (g0 > 2046) g0 = 2046;
            int g1 = un + row + 32; if (g1 > 2046) g1 = 2046;
            pf_l1(rpe + (size_t)g0 * 64 + (t & 15) * 4);
            pf_l1(rpe + (size_t)g1 * 64 + (t & 15) * 4);
            if (tile < NT - 2) {
                pf_l2(kp + (size_t)(row + 64) * 64 + (t & 15) * 4);
                pf_l2(kp + (size_t)(row + 96) * 64 + (t & 15) * 4);
                pf_l2(vp + (size_t)(row + 64) * 64 + (t & 15) * 4);
                pf_l2(vp + (size_t)(row + 96) * 64 + (t & 15) * 4);
            }
        }

        // ---- SV MMAs: O += S V (3-split; vB cached) ----
        {
            uint32_t vB[4][2][2];
            #pragma unroll
            for (int kk = 0; kk < 4; ++kk)
                #pragma unroll
                for (int nt = 0; nt < 2; ++nt)
                    ldmBT(vB[kk][nt], sb + V_HI +
                          ((((uint32_t)(kk*16) << 7) + voff +
                            (uint32_t)(wj*32 + nt*16)) ^ xl));
            #pragma unroll
            for (int kk = 0; kk < 4; ++kk) {
                uint32_t A[2][4];
                #pragma unroll
                for (int mt = 0; mt < 2; ++mt)
                    ldmA(A[mt], sb + S_HI +
                         ((((uint32_t)(wi*32 + mt*16) << 7) + aoff + kk*32) ^ xl));
                #pragma unroll
                for (int mt = 0; mt < 2; ++mt)     // S_HI x V_HI
                    #pragma unroll
                    for (int nt = 0; nt < 2; ++nt)
                        mma16816(oacc[mt][nt], A[mt], vB[kk][nt]);
                uint32_t B[2][2];
                #pragma unroll
                for (int nt = 0; nt < 2; ++nt)
                    ldmBT(B[nt], sb + V_LO +
                          ((((uint32_t)(kk*16) << 7) + voff +
                            (uint32_t)(wj*32 + nt*16)) ^ xl));
                #pragma unroll
                for (int mt = 0; mt < 2; ++mt)     // S_HI x V_LO
                    #pragma unroll
                    for (int nt = 0; nt < 2; ++nt)
                        mma16816(oacc[mt][nt], A[mt], B[nt]);
                uint32_t A2[2][4];
                #pragma unroll
                for (int mt = 0; mt < 2; ++mt)
                    ldmA(A2[mt], sb + S_LO +
                         ((((uint32_t)(wi*32 + mt*16) << 7) + aoff + kk*32) ^ xl));
                #pragma unroll
                for (int mt = 0; mt < 2; ++mt)     // S_LO x V_HI
                    #pragma unroll
                    for (int nt = 0; nt < 2; ++nt)
                        mma16816(oacc[mt][nt], A2[mt], vB[kk][nt]);
            }
        }
    }

    // ---- reduce denominators ----
    #pragma unroll
    for (int u = 0; u < 4; ++u) {
        float s = dsum[u];
        s += __shfl_xor_sync(0xffffffffu, s, 1);
        s += __shfl_xor_sync(0xffffffffu, s, 2);
        if ((lane & 3) == 0)
            atomicAdd(&Dsm[wi*32 + (u >> 1)*16 + qr + ((u & 1) << 3)], s);
    }
    __syncthreads();

    // ---- epilogue ----
    #pragma unroll
    for (int mt = 0; mt < 2; ++mt)
        #pragma unroll
        for (int nt = 0; nt < 2; ++nt) {
            int ii = wi*32 + mt*16 + qr;
            int d0 = wj*16 + nt*8 + qc;
            float inv0 = 1.f / Dsm[ii];
            float inv1 = 1.f / Dsm[ii + 8];
            float* o0 = out + ((size_t)(bh * NSEQ + i0 + ii)) * 64 + d0;
            *(float2*)o0 = make_float2(oacc[mt][nt][0] * inv0, oacc[mt][nt][1] * inv0);
            *(float2*)(o0 + 8 * 64) =
                make_float2(oacc[mt][nt][2] * inv1, oacc[mt][nt][3] * inv1);
        }
}

extern "C" void kernel_launch(void* const* d_in, const int* in_sizes, int n_in,
                              void* d_out, int out_size)
{
    const float* q   = (const float*)d_in[0];
    const float* k   = (const float*)d_in[1];
    const float* v   = (const float*)d_in[2];
    // d_in[3] = drop_noise (unused)
    const float* rpe = (const float*)d_in[4];
    float* out = (float*)d_out;

    cudaFuncSetAttribute(fast_attn_hmma,
                         cudaFuncAttributeMaxDynamicSharedMemorySize, SMEM_BYTES);
    dim3 grid(NSEQ / BI, 16);   // 8 x 16 = 128 CTAs, one wave
    fast_attn_hmma<<<grid, 512, SMEM_BYTES>>>(q, k, v, rpe, out);
}

// round 17
// speedup vs baseline: 1.1979x; 1.0185x over previous
#include <cuda_runtime.h>
#include <cuda_bf16.h>
#include <cstdint>

// Degree-2 Taylor attention with RPE via warp-level mma.sync (bf16 x3-split)
// + rolling band ring + L1 prefetch + per-wi-group named barriers
// + kk-outer operand reuse in band/QK (B_HI fragments loaded once).
// BI=128, BJ=64, 512 threads (16 warps), grid 8 x 16 = 128 CTAs, 1 CTA/SM.

constexpr int NSEQ = 1024, BI = 128, BJ = 64, NT = NSEQ / BJ;
constexpr int RSTR = 200;   // ring stride in floats

// smem byte offsets
constexpr int Q_HI = 0,      Q_LO = 16384;   // 128x64 bf16
constexpr int K_HI = 32768,  K_LO = 40960;   // 64x64
constexpr int R_HI = 49152,  R_LO = 57344;   // 64 rpe rows
constexpr int V_HI = 65536,  V_LO = 73728;   // 64x64 natural
constexpr int S_HI = 81920,  S_LO = 98304;   // 128x64
constexpr int RING = 114688;                 // 128 x 200 f32 ring
constexpr int DEN  = RING + 128 * RSTR * 4;  // 217088
constexpr int SMEM_BYTES = DEN + 512;        // 217600

#define SWZ(o) ((o) ^ ((((o) >> 7) & 7) << 4))

__device__ __forceinline__ uint32_t smem_u32(const void* p) {
    uint32_t a;
    asm("{ .reg .u64 t; cvta.to.shared.u64 t, %1; cvt.u32.u64 %0, t; }"
        : "=r"(a) : "l"(p));
    return a;
}
__device__ __forceinline__ void named_bar(int id) {
    asm volatile("bar.sync %0, 128;" :: "r"(id) : "memory");
}
__device__ __forceinline__ void ldmA(uint32_t a[4], uint32_t addr) {
    asm volatile("ldmatrix.sync.aligned.m8n8.x4.shared.b16 {%0,%1,%2,%3}, [%4];"
                 : "=r"(a[0]), "=r"(a[1]), "=r"(a[2]), "=r"(a[3]) : "r"(addr));
}
__device__ __forceinline__ void ldmB(uint32_t b[2], uint32_t addr) {
    asm volatile("ldmatrix.sync.aligned.m8n8.x2.shared.b16 {%0,%1}, [%2];"
                 : "=r"(b[0]), "=r"(b[1]) : "r"(addr));
}
__device__ __forceinline__ void ldmBT(uint32_t b[2], uint32_t addr) {
    asm volatile("ldmatrix.sync.aligned.m8n8.x2.trans.shared.b16 {%0,%1}, [%2];"
                 : "=r"(b[0]), "=r"(b[1]) : "r"(addr));
}
__device__ __forceinline__ void mma16816(float d[4], const uint32_t a[4],
                                         const uint32_t b[2]) {
    asm volatile(
        "mma.sync.aligned.m16n8k16.row.col.f32.bf16.bf16.f32 "
        "{%0,%1,%2,%3}, {%4,%5,%6,%7}, {%8,%9}, {%0,%1,%2,%3};"
        : "+f"(d[0]), "+f"(d[1]), "+f"(d[2]), "+f"(d[3])
        : "r"(a[0]), "r"(a[1]), "r"(a[2]), "r"(a[3]), "r"(b[0]), "r"(b[1]));
}
__device__ __forceinline__ void cvt_pair(float a, float b, uint32_t& hi, uint32_t& lo) {
    __nv_bfloat162 h = __floats2bfloat162_rn(a, b);
    float2 hf = __bfloat1622float2(h);
    __nv_bfloat162 l = __floats2bfloat162_rn(a - hf.x, b - hf.y);
    hi = *(uint32_t*)&h;
    lo = *(uint32_t*)&l;
}
__device__ __forceinline__ void pf_l1(const float* p) {
    asm volatile("prefetch.global.L1 [%0];" :: "l"(p));
}

__global__ void __launch_bounds__(512, 1)
fast_attn_hmma(const float* __restrict__ q, const float* __restrict__ k,
               const float* __restrict__ v, const float* __restrict__ rpe,
               float* __restrict__ out)
{
    extern __shared__ __align__(1024) char smc[];
    const uint32_t sb = smem_u32(smc);
    float* Pring = (float*)(smc + RING);
    float* Dsm = (float*)(smc + DEN);

    const int bh = blockIdx.y;
    const int i0 = blockIdx.x * BI;
    const int t = threadIdx.x, lane = t & 31, w = t >> 5;
    const int wi = w >> 2, wj = w & 3;   // warp: rows wi*32..+31, j-cols wj*16..+15
    const int qr = lane >> 2, qc = (lane & 3) * 2;

    const uint32_t xl   = (uint32_t)(lane & 7) << 4;
    const uint32_t xs   = (uint32_t)qr << 4;
    const uint32_t aoff = ((uint32_t)((lane & 7) + (lane & 8)) << 7) |
                          (((uint32_t)(lane >> 4) & 1) << 4);
    const uint32_t boff = ((uint32_t)(lane & 7) << 7) |
                          (((uint32_t)(lane >> 3) & 1) << 4);
    const uint32_t voff = (uint32_t)(lane & 15) << 7;

    const float* qb = q + (size_t)bh * NSEQ * 64;
    const float* kb = k + (size_t)bh * NSEQ * 64;
    const float* vb = v + (size_t)bh * NSEQ * 64;

    // ---- convert Q tile once (128x64 -> bf16 hi/lo) ----
    #pragma unroll
    for (int it = 0; it < 4; ++it) {
        int e = t + it * 512;
        int row = e >> 4, c4 = e & 15;
        float4 x = *(const float4*)(qb + (size_t)(i0 + row) * 64 + c4 * 4);
        uint32_t h0, l0, h1, l1;
        cvt_pair(x.x, x.y, h0, l0);
        cvt_pair(x.z, x.w, h1, l1);
        uint32_t sw = SWZ((uint32_t)(row * 128 + c4 * 8));
        *(uint2*)(smc + Q_HI + sw) = make_uint2(h0, h1);
        *(uint2*)(smc + Q_LO + sw) = make_uint2(l0, l1);
    }
    if (t < 128) Dsm[t] = 0.f;
    __syncthreads();

    // ---- preload Q_HI A-fragments (tile-invariant) ----
    uint32_t qA[2][4][4];
    #pragma unroll
    for (int mt = 0; mt < 2; ++mt)
        #pragma unroll
        for (int kk = 0; kk < 4; ++kk)
            ldmA(qA[mt][kk], sb + Q_HI +
                 ((((uint32_t)(wi*32 + mt*16) << 7) + aoff + kk*32) ^ xl));

    // band MMA + ring stage (kk-outer, B_HI fragments reused across splits)
    auto band_stage = [&](int ustart) {
        float bacc[2][2][4];
        #pragma unroll
        for (int a = 0; a < 2; ++a)
            #pragma unroll
            for (int b = 0; b < 2; ++b)
                #pragma unroll
                for (int r = 0; r < 4; ++r) bacc[a][b][r] = 0.f;
        #pragma unroll
        for (int kk = 0; kk < 4; ++kk) {
            uint32_t Bh[2][2], Bl[2][2], Al[2][4];
            #pragma unroll
            for (int nt = 0; nt < 2; ++nt)
                ldmB(Bh[nt], sb + R_HI +
                     ((((uint32_t)(wj*16 + nt*8) << 7) + boff + kk*32) ^ xl));
            #pragma unroll
            for (int mt = 0; mt < 2; ++mt)     // Q_HI x R_HI
                #pragma unroll
                for (int nt = 0; nt < 2; ++nt)
                    mma16816(bacc[mt][nt], qA[mt][kk], Bh[nt]);
            #pragma unroll
            for (int nt = 0; nt < 2; ++nt)
                ldmB(Bl[nt], sb + R_LO +
                     ((((uint32_t)(wj*16 + nt*8) << 7) + boff + kk*32) ^ xl));
            #pragma unroll
            for (int mt = 0; mt < 2; ++mt)     // Q_HI x R_LO
                #pragma unroll
                for (int nt = 0; nt < 2; ++nt)
                    mma16816(bacc[mt][nt], qA[mt][kk], Bl[nt]);
            #pragma unroll
            for (int mt = 0; mt < 2; ++mt)
                ldmA(Al[mt], sb + Q_LO +
                     ((((uint32_t)(wi*32 + mt*16) << 7) + aoff + kk*32) ^ xl));
            #pragma unroll
            for (int mt = 0; mt < 2; ++mt)     // Q_LO x R_HI (Bh reused)
                #pragma unroll
                for (int nt = 0; nt < 2; ++nt)
                    mma16816(bacc[mt][nt], Al[mt], Bh[nt]);
        }
        const int base_s = ustart % 192;
        #pragma unroll
        for (int mt = 0; mt < 2; ++mt)
            #pragma unroll
            for (int nt = 0; nt < 2; ++nt) {
                int row = wi*32 + mt*16 + qr;
                int slot = base_s + wj*16 + nt*8 + qc;
                *(float2*)&Pring[row * RSTR + slot] =
                    make_float2(bacc[mt][nt][0], bacc[mt][nt][1]);
                *(float2*)&Pring[(row + 8) * RSTR + slot] =
                    make_float2(bacc[mt][nt][2], bacc[mt][nt][3]);
            }
    };

    float oacc[2][2][4];
    float dsum[4];
    #pragma unroll
    for (int a = 0; a < 2; ++a)
        #pragma unroll
        for (int b = 0; b < 2; ++b)
            #pragma unroll
            for (int r = 0; r < 4; ++r) oacc[a][b][r] = 0.f;
    #pragma unroll
    for (int u = 0; u < 4; ++u) dsum[u] = 0.f;

    for (int tile = 0; tile < NT; ++tile) {
        const int j0 = tile * BJ;
        __syncthreads();   // full: prev SV done with S/V; K/V/R writable

        // ---- convert K tile ----
        #pragma unroll
        for (int it = 0; it < 2; ++it) {
            int e = t + it * 512;
            int row = e >> 4, c4 = e & 15;
            float4 x = *(const float4*)(kb + (size_t)(j0 + row) * 64 + c4 * 4);
            uint32_t h0, l0, h1, l1;
            cvt_pair(x.x, x.y, h0, l0);
            cvt_pair(x.z, x.w, h1, l1);
            uint32_t sw = SWZ((uint32_t)(row * 128 + c4 * 8));
            *(uint2*)(smc + K_HI + sw) = make_uint2(h0, h1);
            *(uint2*)(smc + K_LO + sw) = make_uint2(l0, l1);
        }
        // ---- convert V tile (natural [j][d]) ----
        #pragma unroll
        for (int it = 0; it < 2; ++it) {
            int e = t + it * 512;
            int row = e >> 4, c4 = e & 15;
            float4 x = *(const float4*)(vb + (size_t)(j0 + row) * 64 + c4 * 4);
            uint32_t h0, l0, h1, l1;
            cvt_pair(x.x, x.y, h0, l0);
            cvt_pair(x.z, x.w, h1, l1);
            uint32_t sw = SWZ((uint32_t)(row * 128 + c4 * 8));
            *(uint2*)(smc + V_HI + sw) = make_uint2(h0, h1);
            *(uint2*)(smc + V_LO + sw) = make_uint2(l0, l1);
        }

        // ---- band ring: new u-columns (3 groups at tile 0, else 1) ----
        const int ngroups = (tile == 0) ? 3 : 1;
        for (int g = 0; g < ngroups; ++g) {
            const int ustart = i0 + 960 - 64 * tile + 64 * g;
            #pragma unroll
            for (int it = 0; it < 2; ++it) {
                int e = t + it * 512;
                int row = e >> 4, c4 = e & 15;
                int gr = ustart + row; if (gr > 2046) gr = 2046;
                float4 x = *(const float4*)(rpe + (size_t)gr * 64 + c4 * 4);
                uint32_t h0, l0, h1, l1;
                cvt_pair(x.x, x.y, h0, l0);
                cvt_pair(x.z, x.w, h1, l1);
                uint32_t sw = SWZ((uint32_t)(row * 128 + c4 * 8));
                *(uint2*)(smc + R_HI + sw) = make_uint2(h0, h1);
                *(uint2*)(smc + R_LO + sw) = make_uint2(l0, l1);
            }
            __syncthreads();   // full: R (and K/V on g=0) visible to all warps
            band_stage(ustart);
            if (g < ngroups - 1) __syncthreads();   // R reused by next group
        }

        // ---- QK MMAs (kk-outer, K_HI frags reused; overlaps ring-STS) ----
        float zacc[2][2][4];
        #pragma unroll
        for (int a = 0; a < 2; ++a)
            #pragma unroll
            for (int b = 0; b < 2; ++b)
                #pragma unroll
                for (int r = 0; r < 4; ++r) zacc[a][b][r] = 0.f;
        #pragma unroll
        for (int kk = 0; kk < 4; ++kk) {
            uint32_t Bh[2][2], Bl[2][2], Al[2][4];
            #pragma unroll
            for (int nt = 0; nt < 2; ++nt)
                ldmB(Bh[nt], sb + K_HI +
                     ((((uint32_t)(wj*16 + nt*8) << 7) + boff + kk*32) ^ xl));
            #pragma unroll
            for (int mt = 0; mt < 2; ++mt)     // Q_HI x K_HI
                #pragma unroll
                for (int nt = 0; nt < 2; ++nt)
                    mma16816(zacc[mt][nt], qA[mt][kk], Bh[nt]);
            #pragma unroll
            for (int nt = 0; nt < 2; ++nt)
                ldmB(Bl[nt], sb + K_LO +
                     ((((uint32_t)(wj*16 + nt*8) << 7) + boff + kk*32) ^ xl));
            #pragma unroll
            for (int mt = 0; mt < 2; ++mt)     // Q_HI x K_LO
                #pragma unroll
                for (int nt = 0; nt < 2; ++nt)
                    mma16816(zacc[mt][nt], qA[mt][kk], Bl[nt]);
            #pragma unroll
            for (int mt = 0; mt < 2; ++mt)
                ldmA(Al[mt], sb + Q_LO +
                     ((((uint32_t)(wi*32 + mt*16) << 7) + aoff + kk*32) ^ xl));
            #pragma unroll
            for (int mt = 0; mt < 2; ++mt)     // Q_LO x K_HI (Bh reused)
                #pragma unroll
                for (int nt = 0; nt < 2; ++nt)
                    mma16816(zacc[mt][nt], Al[mt], Bh[nt]);
        }
        named_bar(1 + wi);   // A (per-wi): ring rows for this wi staged

        // ---- gather band from ring; s-transform; S store ----
        {
            int gb = (i0 - 64 * tile + 1023) % 192;
            #pragma unroll
            for (int mt = 0; mt < 2; ++mt)
                #pragma unroll
                for (int nt = 0; nt < 2; ++nt)
                    #pragma unroll
                    for (int r = 0; r < 4; ++r) {
                        int ii = wi*32 + mt*16 + qr + ((r >> 1) << 3);
                        int jj = wj*16 + nt*8 + qc + (r & 1);
                        int slot = gb + ii - jj;
                        if (slot >= 192) slot -= 192;
                        zacc[mt][nt][r] += Pring[ii * RSTR + slot];
                    }
        }
        #pragma unroll
        for (int mt = 0; mt < 2; ++mt)
            #pragma unroll
            for (int nt = 0; nt < 2; ++nt)
                #pragma unroll
                for (int r = 0; r < 4; ++r) {
                    float z = zacc[mt][nt][r];
                    float s = fmaf(z, fmaf(z, 0.5f, 1.f), 1.f);
                    zacc[mt][nt][r] = s;
                    dsum[mt * 2 + (r >> 1)] += s;
                }
        #pragma unroll
        for (int mt = 0; mt < 2; ++mt)
            #pragma unroll
            for (int nt = 0; nt < 2; ++nt) {
                int r0 = wi*32 + mt*16 + qr;
                int c0 = wj*16 + nt*8 + qc;
                uint32_t h0, l0, h1, l1;
                cvt_pair(zacc[mt][nt][0], zacc[mt][nt][1], h0, l0);
                cvt_pair(zacc[mt][nt][2], zacc[mt][nt][3], h1, l1);
                uint32_t off0 = ((uint32_t)(r0 * 128 + c0 * 2)) ^ xs;
                *(uint32_t*)(smc + S_HI + off0) = h0;
                *(uint32_t*)(smc + S_LO + off0) = l0;
                *(uint32_t*)(smc + S_HI + off0 + 1024) = h1;
                *(uint32_t*)(smc + S_LO + off0 + 1024) = l1;
            }
        named_bar(1 + wi);   // B (per-wi): this wi's S rows visible

        // ---- L1 prefetch hints for tile t+1 ----
        if (tile < NT - 1 && (t & 7) == 0) {
            int row = t >> 4;
            const float* kp = kb + (size_t)(j0 + 64) * 64;
            const float* vp = vb + (size_t)(j0 + 64) * 64;
            int un = i0 + 960 - 64 * (tile + 1);
            pf_l1(kp + (size_t)row * 64 + (t & 15) * 4);
            pf_l1(kp + (size_t)(row + 32) * 64 + (t & 15) * 4);
            pf_l1(vp + (size_t)row * 64 + (t & 15) * 4);
            pf_l1(vp + (size_t)(row + 32) * 64 + (t & 15) * 4);
            int g0 = un + row;      if (g0 > 2046) g0 = 2046;
            int g1 = un + row + 32; if (g1 > 2046) g1 = 2046;
            pf_l1(rpe + (size_t)g0 * 64 + (t & 15) * 4);
            pf_l1(rpe + (size_t)g1 * 64 + (t & 15) * 4);
        }

        // ---- SV MMAs: O += S V (3-split; vB cached) ----
        {
            uint32_t vB[4][2][2];
            #pragma unroll
            for (int kk = 0; kk < 4; ++kk)
                #pragma unroll
                for (int nt = 0; nt < 2; ++nt)
                    ldmBT(vB[kk][nt], sb + V_HI +
                          ((((uint32_t)(kk*16) << 7) + voff +
                            (uint32_t)(wj*32 + nt*16)) ^ xl));
            #pragma unroll
            for (int kk = 0; kk < 4; ++kk) {
                uint32_t A[2][4];
                #pragma unroll
                for (int mt = 0; mt < 2; ++mt)
                    ldmA(A[mt], sb + S_HI +
                         ((((uint32_t)(wi*32 + mt*16) << 7) + aoff + kk*32) ^ xl));
                #pragma unroll
                for (int mt = 0; mt < 2; ++mt)     // S_HI x V_HI
                    #pragma unroll
                    for (int nt = 0; nt < 2; ++nt)
                        mma16816(oacc[mt][nt], A[mt], vB[kk][nt]);
                uint32_t B[2][2];
                #pragma unroll
                for (int nt = 0; nt < 2; ++nt)
                    ldmBT(B[nt], sb + V_LO +
                          ((((uint32_t)(kk*16) << 7) + voff +
                            (uint32_t)(wj*32 + nt*16)) ^ xl));
                #pragma unroll
                for (int mt = 0; mt < 2; ++mt)     // S_HI x V_LO
                    #pragma unroll
                    for (int nt = 0; nt < 2; ++nt)
                        mma16816(oacc[mt][nt], A[mt], B[nt]);
                uint32_t A2[2][4];
                #pragma unroll
                for (int mt = 0; mt < 2; ++mt)
                    ldmA(A2[mt], sb + S_LO +
                         ((((uint32_t)(wi*32 + mt*16) << 7) + aoff + kk*32) ^ xl));
                #pragma unroll
                for (int mt = 0; mt < 2; ++mt)     // S_LO x V_HI
                    #pragma unroll
                    for (int nt = 0; nt < 2; ++nt)
                        mma16816(oacc[mt][nt], A2[mt], vB[kk][nt]);
            }
        }
    }

    // ---- reduce denominators ----
    #pragma unroll
    for (int u = 0; u < 4; ++u) {
        float s = dsum[u];
        s += __shfl_xor_sync(0xffffffffu, s, 1);
        s += __shfl_xor_sync(0xffffffffu, s, 2);
        if ((lane & 3) == 0)
            atomicAdd(&Dsm[wi*32 + (u >> 1)*16 + qr + ((u & 1) << 3)], s);
    }
    __syncthreads();

    // ---- epilogue ----
    #pragma unroll
    for (int mt = 0; mt < 2; ++mt)
        #pragma unroll
        for (int nt = 0; nt < 2; ++nt) {
            int ii = wi*32 + mt*16 + qr;
            int d0 = wj*16 + nt*8 + qc;
            float inv0 = 1.f / Dsm[ii];
            float inv1 = 1.f / Dsm[ii + 8];
            float* o0 = out + ((size_t)(bh * NSEQ + i0 + ii)) * 64 + d0;
            *(float2*)o0 = make_float2(oacc[mt][nt][0] * inv0, oacc[mt][nt][1] * inv0);
            *(float2*)(o0 + 8 * 64) =
                make_float2(oacc[mt][nt][2] * inv1, oacc[mt][nt][3] * inv1);
        }
}

extern "C" void kernel_launch(void* const* d_in, const int* in_sizes, int n_in,
                              void* d_out, int out_size)
{
    const float* q   = (const float*)d_in[0];
    const float* k   = (const float*)d_in[1];
    const float* v   = (const float*)d_in[2];
    // d_in[3] = drop_noise (unused)
    const float* rpe = (const float*)d_in[4];
    float* out = (float*)d_out;

    cudaFuncSetAttribute(fast_attn_hmma,
                         cudaFuncAttributeMaxDynamicSharedMemorySize, SMEM_BYTES);
    dim3 grid(NSEQ / BI, 16);   // 8 x 16 = 128 CTAs, one wave
    fast_attn_hmma<<<grid, 512, SMEM_BYTES>>>(q, k, v, rpe, out);
}